// round 4
// baseline (speedup 1.0000x reference)
#include <cuda_runtime.h>

#define Cc 256
#define Hh 56
#define Ww 56
#define XPR 80   // padded row stride (floats)
#define XPH 58   // padded rows

// Scratch (device globals; zero-initialized at load, no allocs).
__device__ float g_xp[8 * 256 * XPH * XPR];      // padded x, cols>=58 stay 0
__device__ float g_wpt2[4][256][9][64];          // [cog][ci][tap][co64] = weight*A_w
__device__ float g_w1t[256 * 9 * 16];            // [ci][tap][co] se_w1 transposed
__device__ float g_t[8 * 16 * 56 * 56];          // relu(conv1)
__device__ float g_a[8 * 56 * 56];               // attention map

__device__ __forceinline__ void ffma2(unsigned long long& d, unsigned long long a,
                                      unsigned long long b) {
    asm("fma.rn.f32x2 %0, %1, %2, %0;" : "+l"(d) : "l"(a), "l"(b));
}
__device__ __forceinline__ unsigned long long dup2(float v) {
    unsigned long long u;
    unsigned int r = __float_as_uint(v);
    asm("mov.b64 %0, {%1, %1};" : "=l"(u) : "r"(r));
    return u;
}
__device__ __forceinline__ void cp16(void* s, const void* g) {
    unsigned sa = (unsigned)__cvta_generic_to_shared(s);
    asm volatile("cp.async.cg.shared.global [%0], [%1], 16;" ::"r"(sa), "l"(g));
}
#define CP_COMMIT() asm volatile("cp.async.commit_group;")
#define CP_WAIT0() asm volatile("cp.async.wait_group 0;")

// ---------------------------------------------------------------------------
// Pad x into g_xp (zero border). Cols >= 58 never written -> stay 0.
// ---------------------------------------------------------------------------
__global__ void pad_x(const float* __restrict__ x) {
    int idx = blockIdx.x * 256 + threadIdx.x;
    if (idx >= 8 * 256 * XPH * XPH) return;
    int w = idx % XPH;
    int h = (idx / XPH) % XPH;
    int c = (idx / (XPH * XPH)) % 256;
    int b = idx / (XPH * XPH * 256);
    float v = 0.f;
    if (h >= 1 && h < 57 && w >= 1 && w < 57)
        v = x[((b * 256 + c) * Hh + (h - 1)) * Ww + (w - 1)];
    g_xp[((b * 256 + c) * XPH + h) * XPR + w] = v;
}

// ---------------------------------------------------------------------------
// Prep: g_wpt2[cog][ci][tap][cl] = weight[co,ci,tap]*A_w[ci,tap], co=cog*64+cl
//       g_w1t[ci*144 + tap*16 + co] = se_w1[co,ci,tap]
// ---------------------------------------------------------------------------
__global__ void prep_weights(const float* __restrict__ weight,
                             const float* __restrict__ A_w,
                             const float* __restrict__ se_w1) {
    int idx = blockIdx.x * 256 + threadIdx.x;
    if (idx < 589824) {
        int co = idx & 255;
        int tap = (idx >> 8) % 9;
        int ci = idx / 2304;
        g_wpt2[co >> 6][ci][tap][co & 63] =
            weight[co * 2304 + ci * 9 + tap] * A_w[ci * 9 + tap];
    } else if (idx < 589824 + 36864) {
        int i2 = idx - 589824;
        int co = i2 & 15;
        int tap = (i2 >> 4) % 9;
        int ci = i2 / 144;
        g_w1t[i2] = se_w1[co * 2304 + ci * 9 + tap];
    }
}

// ---------------------------------------------------------------------------
// SE conv1: t = relu(conv3x3(x, se_w1))  [8,16,56,56]
// Block 256 = 8 warps; warp = 8 rows x 4 colgroups (8 cols each).
// Each warp handles 2 co (one f32x2 pair). Tile 8x32. Grid (2,7,8).
// Pipelined cp.async double buffer.
// ---------------------------------------------------------------------------
__global__ __launch_bounds__(256) void conv_se1() {
    __shared__ __align__(16) float xs[2][10][36];
    __shared__ __align__(16) float ws[2][9][16];
    int tid = threadIdx.x;
    int cot = tid >> 5;
    int lane = tid & 31;
    int row = lane >> 2;
    int col0 = (lane & 3) << 3;
    int wt = blockIdx.x, ht = blockIdx.y, b = blockIdx.z;
    int h0 = ht * 8, w0 = wt * 32;

    bool isx = tid < 90;
    int xr = tid / 9, xc = (tid % 9) * 4;
    bool isw = (tid >= 90) && (tid < 126);
    int wi = (tid - 90) * 4;
    const float* xpb = g_xp + (long long)b * 256 * XPH * XPR;

    unsigned long long acc[8];
#pragma unroll
    for (int p = 0; p < 8; p++) acc[p] = 0ULL;

    // prologue: load ci=0 into buf 0
    if (isx) cp16(&xs[0][xr][xc], xpb + (h0 + xr) * XPR + (w0 + xc));
    if (isw) cp16(&ws[0][0][wi], g_w1t + wi);
    CP_COMMIT();

    int cur = 0;
    for (int ci = 0; ci < Cc; ci++) {
        CP_WAIT0();
        __syncthreads();
        if (ci + 1 < Cc) {
            int nb = cur ^ 1;
            if (isx)
                cp16(&xs[nb][xr][xc],
                     xpb + (ci + 1) * XPH * XPR + (h0 + xr) * XPR + (w0 + xc));
            if (isw) cp16(&ws[nb][0][wi], g_w1t + (ci + 1) * 144 + wi);
            CP_COMMIT();
        }
        const float(*X)[36] = xs[cur];
        const float(*W)[16] = ws[cur];
#pragma unroll 1
        for (int dy = 0; dy < 3; dy++) {
            unsigned long long xd[10];
#pragma unroll
            for (int p = 0; p < 10; p++) xd[p] = dup2(X[row + dy][col0 + p]);
#pragma unroll
            for (int dx = 0; dx < 3; dx++) {
                unsigned long long wv =
                    *(const unsigned long long*)&W[dy * 3 + dx][cot << 1];
#pragma unroll
                for (int p = 0; p < 8; p++) ffma2(acc[p], wv, xd[p + dx]);
            }
        }
        cur ^= 1;
    }

    int h = h0 + row;
    int co = cot << 1;
    float* t0 = g_t + ((b * 16 + co) * Hh + h) * Ww;
    float* t1 = t0 + Hh * Ww;
#pragma unroll
    for (int p = 0; p < 8; p++) {
        int w = w0 + col0 + p;
        if (w < Ww) {
            t0[w] = fmaxf(__uint_as_float((unsigned)acc[p]), 0.f);
            t1[w] = fmaxf(__uint_as_float((unsigned)(acc[p] >> 32)), 0.f);
        }
    }
}

// ---------------------------------------------------------------------------
// SE conv2 + sigmoid: a = sigmoid(conv3x3(t, se_w2))  [8,56,56]
// ---------------------------------------------------------------------------
__global__ __launch_bounds__(64) void conv_se2(const float* __restrict__ se_w2) {
    __shared__ float ws[144];
    int tid = threadIdx.x;
    int bh = blockIdx.x;
    int b = bh / Hh, h = bh % Hh;
    for (int i = tid; i < 144; i += 64) ws[i] = se_w2[i];
    __syncthreads();
    if (tid >= Ww) return;
    int w = tid;
    float sum = 0.f;
    for (int ci = 0; ci < 16; ci++) {
        const float* tp = g_t + ((b * 16 + ci) * Hh) * Ww;
#pragma unroll
        for (int dy = 0; dy < 3; dy++) {
            int gh = h + dy - 1;
            if (gh < 0 || gh >= Hh) continue;
#pragma unroll
            for (int dx = 0; dx < 3; dx++) {
                int gw = w + dx - 1;
                if (gw < 0 || gw >= Ww) continue;
                sum += tp[gh * Ww + gw] * ws[ci * 9 + dy * 3 + dx];
            }
        }
    }
    g_a[b * Hh * Ww + h * Ww + w] = 1.f / (1.f + __expf(-sum));
}

// ---------------------------------------------------------------------------
// Main conv: out = conv3x3(x, wpt) * a
// Block 256 = 8 warps (co sub-groups of 8 via 4 f32x2 pairs) x 32 spatial.
// Tile: 64 co x (8 rows x 32 cols). Grid (2,7,32): wt, ht, b*4+cog.
// cp.async double-buffered over ci; one barrier per ci.
// ---------------------------------------------------------------------------
__global__ __launch_bounds__(256, 2) void main_conv(float* __restrict__ out) {
    __shared__ __align__(16) float xs[2][10][36];
    __shared__ __align__(16) float ws[2][9][64];
    int tid = threadIdx.x;
    int cot = tid >> 5;
    int lane = tid & 31;
    int row = lane >> 2;
    int col0 = (lane & 3) << 3;
    int wt = blockIdx.x, ht = blockIdx.y;
    int b = blockIdx.z >> 2, cog = blockIdx.z & 3;
    int h0 = ht * 8, w0 = wt * 32;
    int co_base = cog * 64;

    bool isx = tid < 90;
    int xr = tid / 9, xc = (tid % 9) * 4;
    bool isw = (tid >= 90) && (tid < 234);
    int wi = (tid - 90) * 4;
    const float* xpb = g_xp + (long long)b * 256 * XPH * XPR;
    const float* wpb = &g_wpt2[cog][0][0][0];

    unsigned long long acc[4][8];
#pragma unroll
    for (int j = 0; j < 4; j++)
#pragma unroll
        for (int p = 0; p < 8; p++) acc[j][p] = 0ULL;

    if (isx) cp16(&xs[0][xr][xc], xpb + (h0 + xr) * XPR + (w0 + xc));
    if (isw) cp16(&ws[0][0][wi], wpb + wi);
    CP_COMMIT();

    int cur = 0;
    for (int ci = 0; ci < Cc; ci++) {
        CP_WAIT0();
        __syncthreads();
        if (ci + 1 < Cc) {
            int nb = cur ^ 1;
            if (isx)
                cp16(&xs[nb][xr][xc],
                     xpb + (ci + 1) * XPH * XPR + (h0 + xr) * XPR + (w0 + xc));
            if (isw) cp16(&ws[nb][0][wi], wpb + (ci + 1) * 576 + wi);
            CP_COMMIT();
        }
        const float(*X)[36] = xs[cur];
        const float(*W)[64] = ws[cur];
#pragma unroll 1
        for (int dy = 0; dy < 3; dy++) {
            unsigned long long xd[10];
#pragma unroll
            for (int p = 0; p < 10; p++) xd[p] = dup2(X[row + dy][col0 + p]);
#pragma unroll
            for (int dx = 0; dx < 3; dx++) {
                const unsigned long long* w2 =
                    (const unsigned long long*)&W[dy * 3 + dx][cot << 3];
                unsigned long long wv0 = w2[0], wv1 = w2[1], wv2 = w2[2],
                                  wv3 = w2[3];
#pragma unroll
                for (int p = 0; p < 8; p++) {
                    unsigned long long xv = xd[p + dx];
                    ffma2(acc[0][p], wv0, xv);
                    ffma2(acc[1][p], wv1, xv);
                    ffma2(acc[2][p], wv2, xv);
                    ffma2(acc[3][p], wv3, xv);
                }
            }
        }
        cur ^= 1;
    }

    // Epilogue: unpack pairs, multiply by attention map, store.
    int h = h0 + row;
    const float* ab = g_a + b * Hh * Ww + h * Ww;
    float av[8];
#pragma unroll
    for (int p = 0; p < 8; p++) {
        int w = w0 + col0 + p;
        av[p] = (w < Ww) ? ab[w] : 0.f;
    }
#pragma unroll
    for (int j2 = 0; j2 < 4; j2++) {
        int co = co_base + (cot << 3) + (j2 << 1);
        float* o0 = out + ((b * Cc + co) * Hh + h) * Ww;
        float* o1 = o0 + Hh * Ww;
#pragma unroll
        for (int p = 0; p < 8; p++) {
            int w = w0 + col0 + p;
            if (w < Ww) {
                o0[w] = __uint_as_float((unsigned)acc[j2][p]) * av[p];
                o1[w] = __uint_as_float((unsigned)(acc[j2][p] >> 32)) * av[p];
            }
        }
    }
}

// ---------------------------------------------------------------------------
extern "C" void kernel_launch(void* const* d_in, const int* in_sizes, int n_in,
                              void* d_out, int out_size) {
    const float* x = (const float*)d_in[0];       // [8,256,56,56]
    const float* weight = (const float*)d_in[1];  // [256,256,3,3]
    const float* A_w = (const float*)d_in[2];     // [1,256,3,3]
    const float* se_w1 = (const float*)d_in[3];   // [16,256,3,3]
    const float* se_w2 = (const float*)d_in[4];   // [1,16,3,3]
    float* out = (float*)d_out;                   // [8,256,56,56]

    pad_x<<<(8 * 256 * XPH * XPH + 255) / 256, 256>>>(x);
    prep_weights<<<(589824 + 36864 + 255) / 256, 256>>>(weight, A_w, se_w1);
    conv_se1<<<dim3(2, 7, 8), 256>>>();
    conv_se2<<<8 * Hh, 64>>>(se_w2);
    main_conv<<<dim3(2, 7, 32), 256>>>(out);
}

// round 6
// speedup vs baseline: 1.1033x; 1.1033x over previous
#include <cuda_runtime.h>
#include <cstdint>

#define Cc 256
#define Hh 56
#define Ww 56
#define XPR 80
#define XPH 58

__device__ float g_xt[8 * 58 * 58 * 256];     // NHWC padded tf32, borders stay 0
__device__ float g_wA[2 * 9 * 2 * 128 * 256]; // [hi/lo][tap][mh][co128][ci256]
__device__ float g_xp[8 * 256 * XPH * XPR];   // SE path padded NCHW
__device__ float g_w1t[256 * 9 * 16];
__device__ float g_t[8 * 16 * 56 * 56];
__device__ float g_a[8 * 56 * 56];

__device__ __forceinline__ float to_tf32(float v) {
    uint32_t u;
    asm("cvt.rn.tf32.f32 %0, %1;" : "=r"(u) : "f"(v));
    return __uint_as_float(u);
}
__device__ __forceinline__ void cp16g(void* s, const void* g) {
    unsigned sa = (unsigned)__cvta_generic_to_shared(s);
    asm volatile("cp.async.cg.shared.global [%0], [%1], 16;" ::"r"(sa), "l"(g));
}
#define CP_COMMIT() asm volatile("cp.async.commit_group;")
#define CP_WAIT0() asm volatile("cp.async.wait_group 0;")
#define CP_WAIT1() asm volatile("cp.async.wait_group 1;")

__device__ __forceinline__ void mma8(float* d, const uint32_t* a, uint32_t b0,
                                     uint32_t b1) {
    asm volatile(
        "mma.sync.aligned.m16n8k8.row.col.f32.tf32.tf32.f32 "
        "{%0,%1,%2,%3}, {%4,%5,%6,%7}, {%8,%9}, {%0,%1,%2,%3};"
        : "+f"(d[0]), "+f"(d[1]), "+f"(d[2]), "+f"(d[3])
        : "r"(a[0]), "r"(a[1]), "r"(a[2]), "r"(a[3]), "r"(b0), "r"(b1));
}

// ---------------------------------------------------------------------------
__global__ void pad_x(const float* __restrict__ x) {
    int idx = blockIdx.x * 256 + threadIdx.x;
    if (idx >= 8 * 256 * XPH * XPH) return;
    int w = idx % XPH, h = (idx / XPH) % XPH;
    int c = (idx / (XPH * XPH)) % 256, b = idx / (XPH * XPH * 256);
    float v = 0.f;
    if (h >= 1 && h < 57 && w >= 1 && w < 57)
        v = x[((b * 256 + c) * Hh + (h - 1)) * Ww + (w - 1)];
    g_xp[((b * 256 + c) * XPH + h) * XPR + w] = v;
}

// NCHW -> padded NHWC tf32. block(32,8), grid(2, b*56+h, 8)
__global__ void transpose_x(const float* __restrict__ x) {
    __shared__ float t[32][33];
    int tx = threadIdx.x, ty = threadIdx.y;
    int wt = blockIdx.x, bh = blockIdx.y, cg = blockIdx.z;
    int b = bh / 56, h = bh % 56, w0 = wt * 32;
#pragma unroll
    for (int j = 0; j < 4; j++) {
        int ci = cg * 32 + ty + j * 8, w = w0 + tx;
        float v = 0.f;
        if (w < 56) v = x[((b * 256 + ci) * 56 + h) * 56 + w];
        t[ty + j * 8][tx] = to_tf32(v);
    }
    __syncthreads();
#pragma unroll
    for (int j = 0; j < 4; j++) {
        int w = w0 + ty + j * 8, ci = cg * 32 + tx;
        if (w < 56)
            g_xt[(((size_t)(b * 58) + (h + 1)) * 58 + (w + 1)) * 256 + ci] =
                t[tx][ty + j * 8];
    }
}

__global__ void prep_w(const float* __restrict__ weight, const float* __restrict__ A_w,
                       const float* __restrict__ se_w1) {
    int idx = blockIdx.x * 256 + threadIdx.x;
    if (idx < 589824) {
        int co = idx & 255, tap = (idx >> 8) % 9, ci = idx / 2304;
        float wp = weight[co * 2304 + ci * 9 + tap] * A_w[ci * 9 + tap];
        float hi = to_tf32(wp), lo = to_tf32(wp - hi);
        int mh = co >> 7, col = co & 127;
        g_wA[(size_t)(((0 * 9 + tap) * 2 + mh) * 128 + col) * 256 + ci] = hi;
        g_wA[(size_t)(((1 * 9 + tap) * 2 + mh) * 128 + col) * 256 + ci] = lo;
    } else if (idx < 589824 + 36864) {
        int i2 = idx - 589824;
        int co = i2 & 15, tap = (i2 >> 4) % 9, ci = i2 / 144;
        g_w1t[i2] = se_w1[co * 2304 + ci * 9 + tap];
    }
}

// ---------------------------------------------------------------------------
// SE conv1 (proven R3 kernel)
// ---------------------------------------------------------------------------
__global__ __launch_bounds__(256) void conv_se1() {
    __shared__ __align__(16) float xs[2][10][36];
    __shared__ __align__(16) float ws[2][9][16];
    int tid = threadIdx.x, cot = tid >> 5, lane = tid & 31;
    int row = lane >> 2, col0 = (lane & 3) << 3;
    int wt = blockIdx.x, ht = blockIdx.y, b = blockIdx.z;
    int h0 = ht * 8, w0 = wt * 32;
    bool isx = tid < 90;
    int xr = tid / 9, xc = (tid % 9) * 4;
    bool isw = (tid >= 90) && (tid < 126);
    int wi = (tid - 90) * 4;
    const float* xpb = g_xp + (long long)b * 256 * XPH * XPR;
    unsigned long long acc[8];
#pragma unroll
    for (int p = 0; p < 8; p++) acc[p] = 0ULL;
    if (isx) cp16g(&xs[0][xr][xc], xpb + (h0 + xr) * XPR + (w0 + xc));
    if (isw) cp16g(&ws[0][0][wi], g_w1t + wi);
    CP_COMMIT();
    int cur = 0;
    for (int ci = 0; ci < Cc; ci++) {
        CP_WAIT0();
        __syncthreads();
        if (ci + 1 < Cc) {
            int nb = cur ^ 1;
            if (isx)
                cp16g(&xs[nb][xr][xc],
                      xpb + (ci + 1) * XPH * XPR + (h0 + xr) * XPR + (w0 + xc));
            if (isw) cp16g(&ws[nb][0][wi], g_w1t + (ci + 1) * 144 + wi);
            CP_COMMIT();
        }
        const float(*X)[36] = xs[cur];
        const float(*W)[16] = ws[cur];
#pragma unroll 1
        for (int dy = 0; dy < 3; dy++) {
            unsigned long long xd[10];
#pragma unroll
            for (int p = 0; p < 10; p++) {
                unsigned int rr = __float_as_uint(X[row + dy][col0 + p]);
                asm("mov.b64 %0, {%1, %1};" : "=l"(xd[p]) : "r"(rr));
            }
#pragma unroll
            for (int dx = 0; dx < 3; dx++) {
                unsigned long long wv =
                    *(const unsigned long long*)&W[dy * 3 + dx][cot << 1];
#pragma unroll
                for (int p = 0; p < 8; p++)
                    asm("fma.rn.f32x2 %0, %1, %2, %0;"
                        : "+l"(acc[p]) : "l"(wv), "l"(xd[p + dx]));
            }
        }
        cur ^= 1;
    }
    int h = h0 + row, co = cot << 1;
    float* t0 = g_t + ((b * 16 + co) * Hh + h) * Ww;
    float* t1 = t0 + Hh * Ww;
#pragma unroll
    for (int p = 0; p < 8; p++) {
        int w = w0 + col0 + p;
        if (w < Ww) {
            t0[w] = fmaxf(__uint_as_float((unsigned)acc[p]), 0.f);
            t1[w] = fmaxf(__uint_as_float((unsigned)(acc[p] >> 32)), 0.f);
        }
    }
}

__global__ __launch_bounds__(64) void conv_se2(const float* __restrict__ se_w2) {
    __shared__ float ws[144];
    int tid = threadIdx.x, bh = blockIdx.x;
    int b = bh / Hh, h = bh % Hh;
    for (int i = tid; i < 144; i += 64) ws[i] = se_w2[i];
    __syncthreads();
    if (tid >= Ww) return;
    int w = tid;
    float sum = 0.f;
    for (int ci = 0; ci < 16; ci++) {
        const float* tp = g_t + ((b * 16 + ci) * Hh) * Ww;
#pragma unroll
        for (int dy = 0; dy < 3; dy++) {
            int gh = h + dy - 1;
            if (gh < 0 || gh >= Hh) continue;
#pragma unroll
            for (int dx = 0; dx < 3; dx++) {
                int gw = w + dx - 1;
                if (gw < 0 || gw >= Ww) continue;
                sum += tp[gh * Ww + gw] * ws[ci * 9 + dy * 3 + dx];
            }
        }
    }
    g_a[b * Hh * Ww + h * Ww + w] = 1.f / (1.f + __expf(-sum));
}

// ---------------------------------------------------------------------------
// main_mma: tf32 mma.sync shift-conv.
// CTA 128co x 224n (4 rows x 56). grid(14 ht, 8 b, 2 mh), block 256 (8 warps).
// Warp = 32co x 112n = 2 x 14 m16n8k8 tiles. K: 9 taps x 8 ci32-chunks x hi/lo.
// 2-stage cp.async. smem stride 36 -> conflict-free frag LDS.
// ---------------------------------------------------------------------------
#define STG 17280  // floats per stage: A 2*128*36 + B 224*36
#define MAIN_SMEM (2 * STG * 4)

__global__ __launch_bounds__(256, 1) void main_mma(float* __restrict__ out) {
    extern __shared__ __align__(16) float sm[];
    int tid = threadIdx.x, lane = tid & 31, wid = tid >> 5;
    int ht = blockIdx.x, b = blockIdx.y, mh = blockIdx.z;
    int h0 = ht * 4;
    int mw = (wid >> 1) * 32, nw = (wid & 1) * 112;
    int g = lane >> 2, t = lane & 3;

    float d[2][14][4];
#pragma unroll
    for (int mt = 0; mt < 2; mt++)
#pragma unroll
        for (int nt = 0; nt < 14; nt++)
#pragma unroll
            for (int r = 0; r < 4; r++) d[mt][nt][r] = 0.f;

    auto load_chunk = [&](int s, int it) {
        int tap = it / 8, cic = it & 7;
        int dy = tap / 3, dx = tap % 3;
        float* As = sm + s * STG;
        float* Bs = As + 9216;
        const float* aH = g_wA + (size_t)(((0 * 9 + tap) * 2 + mh) * 128) * 256 + cic * 32;
        const float* aL = g_wA + (size_t)(((1 * 9 + tap) * 2 + mh) * 128) * 256 + cic * 32;
        for (int i = tid; i < 1024; i += 256) {
            int co = i >> 3, sg = i & 7;
            cp16g(As + co * 36 + sg * 4, aH + co * 256 + sg * 4);
            cp16g(As + 4608 + co * 36 + sg * 4, aL + co * 256 + sg * 4);
        }
        const float* bsrc =
            g_xt + (size_t)((b * 58 + h0 + dy) * 58 + dx) * 256 + cic * 32;
        for (int i = tid; i < 1792; i += 256) {
            int n = i >> 3, sg = i & 7;
            int r = n / 56, w = n - r * 56;
            cp16g(Bs + n * 36 + sg * 4, bsrc + (size_t)(r * 58 + w) * 256 + sg * 4);
        }
        CP_COMMIT();
    };

    load_chunk(0, 0);

    for (int it = 0; it < 72; it++) {
        int s = it & 1;
        __syncthreads();
        bool pf = (it + 1 < 72);
        if (pf) load_chunk(s ^ 1, it + 1);
        if (pf) CP_WAIT1();
        else CP_WAIT0();
        __syncthreads();
        const float* As0 = sm + s * STG;
        const float* Bs = As0 + 9216;
#pragma unroll
        for (int sel = 0; sel < 2; sel++) {
            const float* A = As0 + sel * 4608;
#pragma unroll
            for (int k8 = 0; k8 < 4; k8++) {
                int k0 = k8 * 8;
                uint32_t a[2][4];
#pragma unroll
                for (int mt = 0; mt < 2; mt++) {
                    const float* ap = A + (mw + mt * 16 + g) * 36 + k0 + t;
                    a[mt][0] = __float_as_uint(ap[0]);
                    a[mt][1] = __float_as_uint(ap[8 * 36]);
                    a[mt][2] = __float_as_uint(ap[4]);
                    a[mt][3] = __float_as_uint(ap[8 * 36 + 4]);
                }
#pragma unroll
                for (int nt = 0; nt < 14; nt++) {
                    const float* bp = Bs + (nw + nt * 8 + g) * 36 + k0 + t;
                    uint32_t b0 = __float_as_uint(bp[0]);
                    uint32_t b1 = __float_as_uint(bp[4]);
                    mma8(d[0][nt], a[0], b0, b1);
                    mma8(d[1][nt], a[1], b0, b1);
                }
            }
        }
    }

    // Epilogue: scale by attention map, store.
    const float* ga = g_a + b * 3136;
#pragma unroll
    for (int mt = 0; mt < 2; mt++) {
        int co = mh * 128 + mw + mt * 16 + g;
        float* ob = out + (size_t)(b * 256 + co) * 3136;
        float* ob2 = ob + 8 * 3136;
#pragma unroll
        for (int nt = 0; nt < 14; nt++) {
            int n = nw + nt * 8 + t * 2;
            int r0 = n / 56, wc = n - r0 * 56;
            int off = (h0 + r0) * 56 + wc;
            float a0 = ga[off], a1 = ga[off + 1];
            ob[off] = d[mt][nt][0] * a0;
            ob[off + 1] = d[mt][nt][1] * a1;
            ob2[off] = d[mt][nt][2] * a0;
            ob2[off + 1] = d[mt][nt][3] * a1;
        }
    }
}

// ---------------------------------------------------------------------------
extern "C" void kernel_launch(void* const* d_in, const int* in_sizes, int n_in,
                              void* d_out, int out_size) {
    const float* x = (const float*)d_in[0];
    const float* weight = (const float*)d_in[1];
    const float* A_w = (const float*)d_in[2];
    const float* se_w1 = (const float*)d_in[3];
    const float* se_w2 = (const float*)d_in[4];
    float* out = (float*)d_out;

    cudaFuncSetAttribute(main_mma, cudaFuncAttributeMaxDynamicSharedMemorySize,
                         MAIN_SMEM);
    pad_x<<<(8 * 256 * XPH * XPH + 255) / 256, 256>>>(x);
    transpose_x<<<dim3(2, 8 * 56, 8), dim3(32, 8)>>>(x);
    prep_w<<<(589824 + 36864 + 255) / 256, 256>>>(weight, A_w, se_w1);
    conv_se1<<<dim3(2, 7, 8), 256>>>();
    conv_se2<<<8 * Hh, 64>>>(se_w2);
    main_mma<<<dim3(14, 8, 2), 256, MAIN_SMEM>>>(out);
}

// round 7
// speedup vs baseline: 1.5969x; 1.4475x over previous
#include <cuda_runtime.h>
#include <cstdint>

#define Cc 256
#define Hh 56
#define Ww 56
#define XPR 80
#define XPH 58

// ---- device scratch ----
__device__ float g_xt2[8 * 8 * 58 * 58 * 36];        // [b][cich][h58][w58][ci32+pad4], tf32
__device__ float g_wB[2 * 9 * 8 * 2 * 128 * 36];     // [mh][tap][cich][sel][co128][k32+pad4]
__device__ float g_xp[8 * 256 * XPH * XPR];          // SE path padded NCHW
__device__ float g_w1t[256 * 9 * 16];
__device__ float g_t[8 * 16 * 56 * 56];              // raw conv1 sums (atomic)
__device__ float g_a[8 * 56 * 56];

__device__ __forceinline__ uint32_t smem_u32(const void* p) {
    uint32_t a;
    asm("{ .reg .u64 t; cvta.to.shared.u64 t, %1; cvt.u32.u64 %0, t; }" : "=r"(a) : "l"(p));
    return a;
}
__device__ __forceinline__ float to_tf32(float v) {
    uint32_t u;
    asm("cvt.rn.tf32.f32 %0, %1;" : "=r"(u) : "f"(v));
    return __uint_as_float(u);
}
__device__ __forceinline__ void cp16g(void* s, const void* g) {
    unsigned sa = (unsigned)__cvta_generic_to_shared(s);
    asm volatile("cp.async.cg.shared.global [%0], [%1], 16;" ::"r"(sa), "l"(g));
}
#define CP_COMMIT() asm volatile("cp.async.commit_group;")
#define CP_WAIT0() asm volatile("cp.async.wait_group 0;")

__device__ __forceinline__ void mbar_init(uint32_t a, uint32_t c) {
    asm volatile("mbarrier.init.shared::cta.b64 [%0], %1;" ::"r"(a), "r"(c) : "memory");
}
__device__ __forceinline__ void mbar_expect(uint32_t a, uint32_t tx) {
    asm volatile("mbarrier.arrive.expect_tx.shared::cta.b64 _, [%0], %1;" ::"r"(a), "r"(tx)
                 : "memory");
}
__device__ __forceinline__ void mbar_wait(uint32_t a, int ph) {
    asm volatile(
        "{\n\t.reg .pred P;\nW%=:\n\t"
        "mbarrier.try_wait.parity.shared::cta.b64 P, [%0], %1;\n\t"
        "@!P bra W%=;\n\t}" ::"r"(a), "r"(ph) : "memory");
}
__device__ __forceinline__ void bulk_g2s(uint32_t dst, const void* src, uint32_t bytes,
                                         uint32_t mbar) {
    asm volatile(
        "cp.async.bulk.shared::cluster.global.mbarrier::complete_tx::bytes [%0], [%1], %2, [%3];"
        ::"r"(dst), "l"(src), "r"(bytes), "r"(mbar) : "memory");
}
__device__ __forceinline__ void mma8(float* d, const uint32_t* a, uint32_t b0,
                                     uint32_t b1) {
    asm volatile(
        "mma.sync.aligned.m16n8k8.row.col.f32.tf32.tf32.f32 "
        "{%0,%1,%2,%3}, {%4,%5,%6,%7}, {%8,%9}, {%0,%1,%2,%3};"
        : "+f"(d[0]), "+f"(d[1]), "+f"(d[2]), "+f"(d[3])
        : "r"(a[0]), "r"(a[1]), "r"(a[2]), "r"(a[3]), "r"(b0), "r"(b1));
}

// ---------------------------------------------------------------------------
__global__ void pad_x(const float* __restrict__ x) {
    int idx = blockIdx.x * 256 + threadIdx.x;
    if (idx >= 8 * 256 * XPH * XPH) return;
    int w = idx % XPH, h = (idx / XPH) % XPH;
    int c = (idx / (XPH * XPH)) % 256, b = idx / (XPH * XPH * 256);
    float v = 0.f;
    if (h >= 1 && h < 57 && w >= 1 && w < 57)
        v = x[((b * 256 + c) * Hh + (h - 1)) * Ww + (w - 1)];
    g_xp[((b * 256 + c) * XPH + h) * XPR + w] = v;
}

// NCHW -> [b][cich][h58][w58][36] padded tf32. block(32,8), grid(2, 448, 8)
__global__ void transpose_x(const float* __restrict__ x) {
    __shared__ float t[32][33];
    int tx = threadIdx.x, ty = threadIdx.y;
    int wt = blockIdx.x, bh = blockIdx.y, cg = blockIdx.z;
    int b = bh / 56, h = bh % 56, w0 = wt * 32;
#pragma unroll
    for (int j = 0; j < 4; j++) {
        int ci = cg * 32 + ty + j * 8, w = w0 + tx;
        float v = 0.f;
        if (w < 56) v = x[((b * 256 + ci) * 56 + h) * 56 + w];
        t[ty + j * 8][tx] = to_tf32(v);
    }
    __syncthreads();
#pragma unroll
    for (int j = 0; j < 4; j++) {
        int w = w0 + ty + j * 8, ci = tx;
        if (w < 56)
            g_xt2[((size_t)((b * 8 + cg) * 58 + h + 1) * 58 + (w + 1)) * 36 + ci] =
                t[tx][ty + j * 8];
    }
}

// weights -> g_wB padded-36 hi/lo; se_w1 transpose
__global__ void prep_w(const float* __restrict__ weight, const float* __restrict__ A_w,
                       const float* __restrict__ se_w1) {
    int idx = blockIdx.x * 256 + threadIdx.x;
    if (idx < 589824) {
        int k = idx & 31;
        int co = (idx >> 5) & 127;
        int rest = idx >> 12;
        int cich = rest & 7;
        rest >>= 3;
        int tap = rest % 9, mh = rest / 9;
        int ci = cich * 32 + k, cog = mh * 128 + co;
        float wp = weight[cog * 2304 + ci * 9 + tap] * A_w[ci * 9 + tap];
        float hi = to_tf32(wp), lo = to_tf32(wp - hi);
        size_t base = ((size_t)(((mh * 9 + tap) * 8 + cich) * 2) * 128 + co) * 36 + k;
        g_wB[base] = hi;
        g_wB[base + 128 * 36] = lo;
    } else if (idx < 589824 + 36864) {
        int i2 = idx - 589824;
        int co = i2 & 15, tap = (i2 >> 4) % 9, ci = i2 / 144;
        g_w1t[i2] = se_w1[co * 2304 + ci * 9 + tap];
    }
}

__global__ void zero_t() {
    int idx = blockIdx.x * 256 + threadIdx.x;
    if (idx < 8 * 16 * 56 * 56) g_t[idx] = 0.f;
}

// ---------------------------------------------------------------------------
// SE conv1: ci-split x4, atomic accumulate raw sums into g_t.
// grid (2 wt, 14 ht, 32 z=b*4+cq), block 256 = 8 warps x (2 co each).
// Tile 4 rows x 32 cols; lane: row=lane>>3, col0=(lane&7)*4.
// ---------------------------------------------------------------------------
__global__ __launch_bounds__(256) void conv_se1() {
    __shared__ __align__(16) float xs[2][6][36];
    __shared__ __align__(16) float ws[2][9][16];
    int tid = threadIdx.x, cot = tid >> 5, lane = tid & 31;
    int row = lane >> 3, col0 = (lane & 7) << 2;
    int wt = blockIdx.x, ht = blockIdx.y, z = blockIdx.z;
    int b = z >> 2, cq = z & 3;
    int h0 = ht * 4, w0 = wt * 32;
    int ci0 = cq * 64;

    bool isx = tid < 54;
    int xr = tid / 9, xc = (tid % 9) * 4;
    bool isw = (tid >= 54) && (tid < 90);
    int wi = (tid - 54) * 4;
    const float* xpb = g_xp + (long long)b * 256 * XPH * XPR;

    unsigned long long acc[4];
#pragma unroll
    for (int p = 0; p < 4; p++) acc[p] = 0ULL;

    if (isx) cp16g(&xs[0][xr][xc], xpb + (size_t)ci0 * XPH * XPR + (h0 + xr) * XPR + (w0 + xc));
    if (isw) cp16g(&ws[0][0][wi], g_w1t + ci0 * 144 + wi);
    CP_COMMIT();

    int cur = 0;
    for (int i = 0; i < 64; i++) {
        CP_WAIT0();
        __syncthreads();
        if (i + 1 < 64) {
            int nb = cur ^ 1, ci = ci0 + i + 1;
            if (isx)
                cp16g(&xs[nb][xr][xc],
                      xpb + (size_t)ci * XPH * XPR + (h0 + xr) * XPR + (w0 + xc));
            if (isw) cp16g(&ws[nb][0][wi], g_w1t + ci * 144 + wi);
            CP_COMMIT();
        }
        const float(*X)[36] = xs[cur];
        const float(*W)[16] = ws[cur];
#pragma unroll
        for (int dy = 0; dy < 3; dy++) {
            unsigned long long xd[6];
#pragma unroll
            for (int p = 0; p < 6; p++) {
                unsigned int rr = __float_as_uint(X[row + dy][col0 + p]);
                asm("mov.b64 %0, {%1, %1};" : "=l"(xd[p]) : "r"(rr));
            }
#pragma unroll
            for (int dx = 0; dx < 3; dx++) {
                unsigned long long wv = *(const unsigned long long*)&W[dy * 3 + dx][cot << 1];
#pragma unroll
                for (int p = 0; p < 4; p++)
                    asm("fma.rn.f32x2 %0, %1, %2, %0;"
                        : "+l"(acc[p]) : "l"(wv), "l"(xd[p + dx]));
            }
        }
        cur ^= 1;
    }
    int h = h0 + row, co = cot << 1;
    float* t0 = g_t + ((b * 16 + co) * Hh + h) * Ww;
#pragma unroll
    for (int p = 0; p < 4; p++) {
        int w = w0 + col0 + p;
        if (w < Ww) {
            atomicAdd(t0 + w, __uint_as_float((unsigned)acc[p]));
            atomicAdd(t0 + Hh * Ww + w, __uint_as_float((unsigned)(acc[p] >> 32)));
        }
    }
}

// SE conv2 + sigmoid; relu applied on read (g_t holds raw sums)
__global__ __launch_bounds__(64) void conv_se2(const float* __restrict__ se_w2) {
    __shared__ float ws[144];
    int tid = threadIdx.x, bh = blockIdx.x;
    int b = bh / Hh, h = bh % Hh;
    for (int i = tid; i < 144; i += 64) ws[i] = se_w2[i];
    __syncthreads();
    if (tid >= Ww) return;
    int w = tid;
    float sum = 0.f;
    for (int ci = 0; ci < 16; ci++) {
        const float* tp = g_t + ((b * 16 + ci) * Hh) * Ww;
#pragma unroll
        for (int dy = 0; dy < 3; dy++) {
            int gh = h + dy - 1;
            if (gh < 0 || gh >= Hh) continue;
#pragma unroll
            for (int dx = 0; dx < 3; dx++) {
                int gw = w + dx - 1;
                if (gw < 0 || gw >= Ww) continue;
                sum += fmaxf(tp[gh * Ww + gw], 0.f) * ws[ci * 9 + dy * 3 + dx];
            }
        }
    }
    g_a[b * Hh * Ww + h * Ww + w] = 1.f / (1.f + __expf(-sum));
}

// ---------------------------------------------------------------------------
// main_mma: tf32 mma.sync shift-conv, cp.async.bulk staging.
// grid(14 ht, 8 b, 2 mh), block 256. CTA = 128co x 224n (4 rows x 56).
// Loop: cich(8){ B halo 6x58x36 one bulk, reused by 9 taps } x tap(9){ A one bulk }.
// smem: A 2x36864B + B 2x50112B = 173952B dynamic; mbars static.
// ---------------------------------------------------------------------------
#define ABF 9216    // floats per A buffer (2 sel x 128 x 36)
#define BBF 12528   // floats per B buffer (6 x 58 x 36)
#define AB_BYTES 36864
#define BB_BYTES 50112
#define MAIN_SMEM ((2 * ABF + 2 * BBF) * 4)

__global__ __launch_bounds__(256, 1) void main_mma(float* __restrict__ out) {
    extern __shared__ __align__(16) float sm[];
    __shared__ __align__(8) unsigned long long mbs[4];  // A0,A1,B0,B1
    uint32_t smb = smem_u32(sm);
    uint32_t mba = smem_u32(mbs);
    int tid = threadIdx.x, lane = tid & 31, wid = tid >> 5;
    int ht = blockIdx.x, b = blockIdx.y, mh = blockIdx.z;
    int h0p = ht * 4;
    int mw = (wid >> 1) * 32, nw = (wid & 1) * 112;
    int g = lane >> 2, t = lane & 3;

    if (tid == 0)
        for (int i = 0; i < 4; i++) mbar_init(mba + i * 8, 1);
    __syncthreads();

    float d[2][14][4];
#pragma unroll
    for (int mt = 0; mt < 2; mt++)
#pragma unroll
        for (int nt = 0; nt < 14; nt++)
#pragma unroll
            for (int r = 0; r < 4; r++) d[mt][nt][r] = 0.f;

    // per-thread B row geometry (n never crosses a row within a tile)
    int rB[14], cB[14];
#pragma unroll
    for (int nt = 0; nt < 14; nt++) {
        int n0 = nw + nt * 8;
        rB[nt] = n0 / 56;
        cB[nt] = n0 % 56 + g;
    }

    auto issueA = [&](int p) {
        int buf = p & 1;
        const float* src = g_wB + (size_t)(((mh * 9 + (p % 9)) * 8 + (p / 9))) * 2 * 128 * 36;
        mbar_expect(mba + buf * 8, AB_BYTES);
        bulk_g2s(smb + buf * AB_BYTES, src, AB_BYTES, mba + buf * 8);
    };
    auto issueB = [&](int c) {
        int buf = c & 1;
        const float* src = g_xt2 + ((size_t)(b * 8 + c) * 58 + h0p) * 58 * 36;
        mbar_expect(mba + 16 + buf * 8, BB_BYTES);
        bulk_g2s(smb + 2 * AB_BYTES + buf * BB_BYTES, src, BB_BYTES, mba + 16 + buf * 8);
    };

    if (tid == 0) {
        issueA(0);
        issueB(0);
    }

    int p = 0;
    for (int c = 0; c < 8; c++) {
        mbar_wait(mba + 16 + (c & 1) * 8, (c >> 1) & 1);
        const float* Bs = sm + 2 * ABF + (c & 1) * BBF;
#pragma unroll 1
        for (int tap = 0; tap < 9; tap++, p++) {
            mbar_wait(mba + (p & 1) * 8, (p >> 1) & 1);
            __syncthreads();
            if (tid == 0) {
                if (p + 1 < 72) issueA(p + 1);
                if (tap == 0 && c + 1 < 8) issueB(c + 1);
            }
            int dy = tap / 3, dx = tap % 3;
            const float* As = sm + (p & 1) * ABF;
            const float* pB[14];
#pragma unroll
            for (int nt = 0; nt < 14; nt++)
                pB[nt] = Bs + ((rB[nt] + dy) * 58 + cB[nt] + dx) * 36 + t;
            const float* pA = As + (mw + g) * 36 + t;
#pragma unroll
            for (int k8 = 0; k8 < 4; k8++) {
                int k0 = k8 * 8;
                uint32_t bf[14][2];
#pragma unroll
                for (int nt = 0; nt < 14; nt++) {
                    bf[nt][0] = __float_as_uint(pB[nt][k0]);
                    bf[nt][1] = __float_as_uint(pB[nt][k0 + 4]);
                }
#pragma unroll
                for (int sel = 0; sel < 2; sel++) {
                    const float* ap0 = pA + sel * 4608 + k0;
                    uint32_t a[2][4];
#pragma unroll
                    for (int mt = 0; mt < 2; mt++) {
                        const float* ap = ap0 + mt * 16 * 36;
                        a[mt][0] = __float_as_uint(ap[0]);
                        a[mt][1] = __float_as_uint(ap[8 * 36]);
                        a[mt][2] = __float_as_uint(ap[4]);
                        a[mt][3] = __float_as_uint(ap[8 * 36 + 4]);
                    }
#pragma unroll
                    for (int nt = 0; nt < 14; nt++) {
                        mma8(d[0][nt], a[0], bf[nt][0], bf[nt][1]);
                        mma8(d[1][nt], a[1], bf[nt][0], bf[nt][1]);
                    }
                }
            }
        }
    }

    // Epilogue: scale by attention map, store (layout validated in R6).
    const float* ga = g_a + b * 3136;
#pragma unroll
    for (int mt = 0; mt < 2; mt++) {
        int co = mh * 128 + mw + mt * 16 + g;
        float* ob = out + (size_t)(b * 256 + co) * 3136;
        float* ob2 = ob + 8 * 3136;
#pragma unroll
        for (int nt = 0; nt < 14; nt++) {
            int n = nw + nt * 8 + t * 2;
            int r0 = n / 56, wc = n - r0 * 56;
            int off = (h0p + r0) * 56 + wc;
            float a0 = ga[off], a1 = ga[off + 1];
            ob[off] = d[mt][nt][0] * a0;
            ob[off + 1] = d[mt][nt][1] * a1;
            ob2[off] = d[mt][nt][2] * a0;
            ob2[off + 1] = d[mt][nt][3] * a1;
        }
    }
}

// ---------------------------------------------------------------------------
extern "C" void kernel_launch(void* const* d_in, const int* in_sizes, int n_in,
                              void* d_out, int out_size) {
    const float* x = (const float*)d_in[0];
    const float* weight = (const float*)d_in[1];
    const float* A_w = (const float*)d_in[2];
    const float* se_w1 = (const float*)d_in[3];
    const float* se_w2 = (const float*)d_in[4];
    float* out = (float*)d_out;

    cudaFuncSetAttribute(main_mma, cudaFuncAttributeMaxDynamicSharedMemorySize, MAIN_SMEM);
    pad_x<<<(8 * 256 * XPH * XPH + 255) / 256, 256>>>(x);
    transpose_x<<<dim3(2, 8 * 56, 8), dim3(32, 8)>>>(x);
    prep_w<<<(589824 + 36864 + 255) / 256, 256>>>(weight, A_w, se_w1);
    zero_t<<<(8 * 16 * 56 * 56 + 255) / 256, 256>>>();
    conv_se1<<<dim3(2, 14, 32), 256>>>();
    conv_se2<<<8 * Hh, 64>>>(se_w2);
    main_mma<<<dim3(14, 8, 2), 256, MAIN_SMEM>>>(out);
}

// round 8
// speedup vs baseline: 2.3195x; 1.4525x over previous
#include <cuda_runtime.h>
#include <cstdint>

#define Cc 256
#define Hh 56
#define Ww 56
#define XPR 80
#define XPH 58

// ---- device scratch ----
__device__ float g_xt2[8 * 8 * 58 * 58 * 36];    // [b][cich][h58][w58][ci32+pad4], tf32
__device__ float g_wB[2 * 9 * 8 * 128 * 36];     // [mh][tap][cich][co128][k32+pad4], tf32
__device__ float g_xp[8 * 256 * XPH * XPR];      // SE path padded NCHW
__device__ float g_w1t[256 * 9 * 16];
__device__ float g_t[8 * 16 * 56 * 56];          // raw conv1 sums (atomic)
__device__ float g_a[8 * 56 * 56];

__device__ __forceinline__ uint32_t smem_u32(const void* p) {
    uint32_t a;
    asm("{ .reg .u64 t; cvta.to.shared.u64 t, %1; cvt.u32.u64 %0, t; }" : "=r"(a) : "l"(p));
    return a;
}
__device__ __forceinline__ float to_tf32(float v) {
    uint32_t u;
    asm("cvt.rn.tf32.f32 %0, %1;" : "=r"(u) : "f"(v));
    return __uint_as_float(u);
}
__device__ __forceinline__ void cp16g(void* s, const void* g) {
    unsigned sa = (unsigned)__cvta_generic_to_shared(s);
    asm volatile("cp.async.cg.shared.global [%0], [%1], 16;" ::"r"(sa), "l"(g));
}
#define CP_COMMIT() asm volatile("cp.async.commit_group;")
#define CP_WAIT0() asm volatile("cp.async.wait_group 0;")

__device__ __forceinline__ void mbar_init(uint32_t a, uint32_t c) {
    asm volatile("mbarrier.init.shared::cta.b64 [%0], %1;" ::"r"(a), "r"(c) : "memory");
}
__device__ __forceinline__ void mbar_expect(uint32_t a, uint32_t tx) {
    asm volatile("mbarrier.arrive.expect_tx.shared::cta.b64 _, [%0], %1;" ::"r"(a), "r"(tx)
                 : "memory");
}
__device__ __forceinline__ void mbar_wait(uint32_t a, int ph) {
    asm volatile(
        "{\n\t.reg .pred P;\nW%=:\n\t"
        "mbarrier.try_wait.parity.shared::cta.b64 P, [%0], %1;\n\t"
        "@!P bra W%=;\n\t}" ::"r"(a), "r"(ph) : "memory");
}
__device__ __forceinline__ void bulk_g2s(uint32_t dst, const void* src, uint32_t bytes,
                                         uint32_t mbar) {
    asm volatile(
        "cp.async.bulk.shared::cluster.global.mbarrier::complete_tx::bytes [%0], [%1], %2, [%3];"
        ::"r"(dst), "l"(src), "r"(bytes), "r"(mbar) : "memory");
}
__device__ __forceinline__ void mma8(float* d, const uint32_t* a, uint32_t b0,
                                     uint32_t b1) {
    asm volatile(
        "mma.sync.aligned.m16n8k8.row.col.f32.tf32.tf32.f32 "
        "{%0,%1,%2,%3}, {%4,%5,%6,%7}, {%8,%9}, {%0,%1,%2,%3};"
        : "+f"(d[0]), "+f"(d[1]), "+f"(d[2]), "+f"(d[3])
        : "r"(a[0]), "r"(a[1]), "r"(a[2]), "r"(a[3]), "r"(b0), "r"(b1));
}

// ---------------------------------------------------------------------------
__global__ void pad_x(const float* __restrict__ x) {
    int idx = blockIdx.x * 256 + threadIdx.x;
    if (idx >= 8 * 256 * XPH * XPH) return;
    int w = idx % XPH, h = (idx / XPH) % XPH;
    int c = (idx / (XPH * XPH)) % 256, b = idx / (XPH * XPH * 256);
    float v = 0.f;
    if (h >= 1 && h < 57 && w >= 1 && w < 57)
        v = x[((b * 256 + c) * Hh + (h - 1)) * Ww + (w - 1)];
    g_xp[((b * 256 + c) * XPH + h) * XPR + w] = v;
}

// NCHW -> [b][cich][h58][w58][36] padded tf32. block(32,8), grid(2, 448, 8)
__global__ void transpose_x(const float* __restrict__ x) {
    __shared__ float t[32][33];
    int tx = threadIdx.x, ty = threadIdx.y;
    int wt = blockIdx.x, bh = blockIdx.y, cg = blockIdx.z;
    int b = bh / 56, h = bh % 56, w0 = wt * 32;
#pragma unroll
    for (int j = 0; j < 4; j++) {
        int ci = cg * 32 + ty + j * 8, w = w0 + tx;
        float v = 0.f;
        if (w < 56) v = x[((b * 256 + ci) * 56 + h) * 56 + w];
        t[ty + j * 8][tx] = to_tf32(v);
    }
    __syncthreads();
#pragma unroll
    for (int j = 0; j < 4; j++) {
        int w = w0 + ty + j * 8, ci = tx;
        if (w < 56)
            g_xt2[((size_t)((b * 8 + cg) * 58 + h + 1) * 58 + (w + 1)) * 36 + ci] =
                t[tx][ty + j * 8];
    }
}

// weights -> g_wB padded-36 single tf32; se_w1 transpose
__global__ void prep_w(const float* __restrict__ weight, const float* __restrict__ A_w,
                       const float* __restrict__ se_w1) {
    int idx = blockIdx.x * 256 + threadIdx.x;
    if (idx < 589824) {
        int k = idx & 31;
        int co = (idx >> 5) & 127;
        int rest = idx >> 12;
        int cich = rest & 7;
        rest >>= 3;
        int tap = rest % 9, mh = rest / 9;
        int ci = cich * 32 + k, cog = mh * 128 + co;
        float wp = weight[cog * 2304 + ci * 9 + tap] * A_w[ci * 9 + tap];
        g_wB[((size_t)((mh * 9 + tap) * 8 + cich) * 128 + co) * 36 + k] = to_tf32(wp);
    } else if (idx < 589824 + 36864) {
        int i2 = idx - 589824;
        int co = i2 & 15, tap = (i2 >> 4) % 9, ci = i2 / 144;
        g_w1t[i2] = se_w1[co * 2304 + ci * 9 + tap];
    }
}

__global__ void zero_t() {
    int idx = blockIdx.x * 256 + threadIdx.x;
    if (idx < 8 * 16 * 56 * 56) g_t[idx] = 0.f;
}

// ---------------------------------------------------------------------------
// SE conv1: ci-split x4, atomic accumulate raw sums into g_t. (proven R7)
// ---------------------------------------------------------------------------
__global__ __launch_bounds__(256) void conv_se1() {
    __shared__ __align__(16) float xs[2][6][36];
    __shared__ __align__(16) float ws[2][9][16];
    int tid = threadIdx.x, cot = tid >> 5, lane = tid & 31;
    int row = lane >> 3, col0 = (lane & 7) << 2;
    int wt = blockIdx.x, ht = blockIdx.y, z = blockIdx.z;
    int b = z >> 2, cq = z & 3;
    int h0 = ht * 4, w0 = wt * 32;
    int ci0 = cq * 64;

    bool isx = tid < 54;
    int xr = tid / 9, xc = (tid % 9) * 4;
    bool isw = (tid >= 54) && (tid < 90);
    int wi = (tid - 54) * 4;
    const float* xpb = g_xp + (long long)b * 256 * XPH * XPR;

    unsigned long long acc[4];
#pragma unroll
    for (int p = 0; p < 4; p++) acc[p] = 0ULL;

    if (isx) cp16g(&xs[0][xr][xc], xpb + (size_t)ci0 * XPH * XPR + (h0 + xr) * XPR + (w0 + xc));
    if (isw) cp16g(&ws[0][0][wi], g_w1t + ci0 * 144 + wi);
    CP_COMMIT();

    int cur = 0;
    for (int i = 0; i < 64; i++) {
        CP_WAIT0();
        __syncthreads();
        if (i + 1 < 64) {
            int nb = cur ^ 1, ci = ci0 + i + 1;
            if (isx)
                cp16g(&xs[nb][xr][xc],
                      xpb + (size_t)ci * XPH * XPR + (h0 + xr) * XPR + (w0 + xc));
            if (isw) cp16g(&ws[nb][0][wi], g_w1t + ci * 144 + wi);
            CP_COMMIT();
        }
        const float(*X)[36] = xs[cur];
        const float(*W)[16] = ws[cur];
#pragma unroll
        for (int dy = 0; dy < 3; dy++) {
            unsigned long long xd[6];
#pragma unroll
            for (int p = 0; p < 6; p++) {
                unsigned int rr = __float_as_uint(X[row + dy][col0 + p]);
                asm("mov.b64 %0, {%1, %1};" : "=l"(xd[p]) : "r"(rr));
            }
#pragma unroll
            for (int dx = 0; dx < 3; dx++) {
                unsigned long long wv = *(const unsigned long long*)&W[dy * 3 + dx][cot << 1];
#pragma unroll
                for (int p = 0; p < 4; p++)
                    asm("fma.rn.f32x2 %0, %1, %2, %0;"
                        : "+l"(acc[p]) : "l"(wv), "l"(xd[p + dx]));
            }
        }
        cur ^= 1;
    }
    int h = h0 + row, co = cot << 1;
    float* t0 = g_t + ((b * 16 + co) * Hh + h) * Ww;
#pragma unroll
    for (int p = 0; p < 4; p++) {
        int w = w0 + col0 + p;
        if (w < Ww) {
            atomicAdd(t0 + w, __uint_as_float((unsigned)acc[p]));
            atomicAdd(t0 + Hh * Ww + w, __uint_as_float((unsigned)(acc[p] >> 32)));
        }
    }
}

// ---------------------------------------------------------------------------
// SE conv2 + sigmoid, smem-staged t tile. grid(14 ht, 8 b), block 224.
// ---------------------------------------------------------------------------
__global__ __launch_bounds__(224) void conv_se2(const float* __restrict__ se_w2) {
    __shared__ float ws[144];
    __shared__ float ts[16][6][58];
    int tid = threadIdx.x;
    int ht = blockIdx.x, b = blockIdx.y;
    int h0 = ht * 4;
    if (tid < 144) ws[tid] = se_w2[tid];
    for (int i = tid; i < 16 * 6 * 58; i += 224) {
        int c = i % 58, r = (i / 58) % 6, ci = i / (58 * 6);
        int gh = h0 + r - 1, gw = c - 1;
        float v = 0.f;
        if (gh >= 0 && gh < Hh && gw >= 0 && gw < Ww)
            v = fmaxf(g_t[((b * 16 + ci) * Hh + gh) * Ww + gw], 0.f);
        ts[ci][r][c] = v;
    }
    __syncthreads();
    int rr = tid / 56, w = tid % 56;
    float sum = 0.f;
#pragma unroll 1
    for (int ci = 0; ci < 16; ci++)
#pragma unroll
        for (int dy = 0; dy < 3; dy++)
#pragma unroll
            for (int dx = 0; dx < 3; dx++)
                sum += ts[ci][rr + dy][w + dx] * ws[ci * 9 + dy * 3 + dx];
    g_a[(b * Hh + h0 + rr) * Ww + w] = 1.f / (1.f + __expf(-sum));
}

// ---------------------------------------------------------------------------
// main_mma: single-pass tf32 mma.sync shift-conv, cp.async.bulk staging.
// grid(2 mh, 14 ht, 8 b) — mh pairs adjacent for B L2 reuse. block 256.
// CTA = 128co x 224n. Loop: cich(8){ B halo bulk, reused by 9 taps }{ A bulk/tap }.
// ---------------------------------------------------------------------------
#define ABF 4608    // floats per A buffer (128 x 36)
#define BBF 12528   // floats per B buffer (6 x 58 x 36)
#define AB_BYTES 18432
#define BB_BYTES 50112
#define MAIN_SMEM ((2 * ABF + 2 * BBF) * 4)

__global__ __launch_bounds__(256, 1) void main_mma(float* __restrict__ out) {
    extern __shared__ __align__(16) float sm[];
    __shared__ __align__(8) unsigned long long mbs[4];  // A0,A1,B0,B1
    uint32_t smb = smem_u32(sm);
    uint32_t mba = smem_u32(mbs);
    int tid = threadIdx.x, lane = tid & 31, wid = tid >> 5;
    int mh = blockIdx.x, ht = blockIdx.y, b = blockIdx.z;
    int h0p = ht * 4;
    int mw = (wid >> 1) * 32, nw = (wid & 1) * 112;
    int g = lane >> 2, t = lane & 3;

    if (tid == 0)
        for (int i = 0; i < 4; i++) mbar_init(mba + i * 8, 1);
    __syncthreads();

    float d[2][14][4];
#pragma unroll
    for (int mt = 0; mt < 2; mt++)
#pragma unroll
        for (int nt = 0; nt < 14; nt++)
#pragma unroll
            for (int r = 0; r < 4; r++) d[mt][nt][r] = 0.f;

    int rB[14], cB[14];
#pragma unroll
    for (int nt = 0; nt < 14; nt++) {
        int n0 = nw + nt * 8;
        rB[nt] = n0 / 56;
        cB[nt] = n0 % 56 + g;
    }

    auto issueA = [&](int p) {
        int buf = p & 1;
        const float* src = g_wB + (size_t)((mh * 9 + (p % 9)) * 8 + (p / 9)) * 128 * 36;
        mbar_expect(mba + buf * 8, AB_BYTES);
        bulk_g2s(smb + buf * AB_BYTES, src, AB_BYTES, mba + buf * 8);
    };
    auto issueB = [&](int c) {
        int buf = c & 1;
        const float* src = g_xt2 + ((size_t)(b * 8 + c) * 58 + h0p) * 58 * 36;
        mbar_expect(mba + 16 + buf * 8, BB_BYTES);
        bulk_g2s(smb + 2 * AB_BYTES + buf * BB_BYTES, src, BB_BYTES, mba + 16 + buf * 8);
    };

    if (tid == 0) {
        issueA(0);
        issueB(0);
    }

    int p = 0;
    for (int c = 0; c < 8; c++) {
        mbar_wait(mba + 16 + (c & 1) * 8, (c >> 1) & 1);
        const float* Bs = sm + 2 * ABF + (c & 1) * BBF;
#pragma unroll 1
        for (int tap = 0; tap < 9; tap++, p++) {
            mbar_wait(mba + (p & 1) * 8, (p >> 1) & 1);
            __syncthreads();
            if (tid == 0) {
                if (p + 1 < 72) issueA(p + 1);
                if (tap == 0 && c + 1 < 8) issueB(c + 1);
            }
            int dy = tap / 3, dx = tap % 3;
            const float* As = sm + (p & 1) * ABF;
            const float* pB[14];
#pragma unroll
            for (int nt = 0; nt < 14; nt++)
                pB[nt] = Bs + ((rB[nt] + dy) * 58 + cB[nt] + dx) * 36 + t;
            const float* pA = As + (mw + g) * 36 + t;
#pragma unroll
            for (int k8 = 0; k8 < 4; k8++) {
                int k0 = k8 * 8;
                uint32_t a[2][4];
#pragma unroll
                for (int mt = 0; mt < 2; mt++) {
                    const float* ap = pA + mt * 16 * 36 + k0;
                    a[mt][0] = __float_as_uint(ap[0]);
                    a[mt][1] = __float_as_uint(ap[8 * 36]);
                    a[mt][2] = __float_as_uint(ap[4]);
                    a[mt][3] = __float_as_uint(ap[8 * 36 + 4]);
                }
#pragma unroll
                for (int nt = 0; nt < 14; nt++) {
                    uint32_t b0 = __float_as_uint(pB[nt][k0]);
                    uint32_t b1 = __float_as_uint(pB[nt][k0 + 4]);
                    mma8(d[0][nt], a[0], b0, b1);
                    mma8(d[1][nt], a[1], b0, b1);
                }
            }
        }
    }

    // Epilogue: scale by attention map, store.
    const float* ga = g_a + b * 3136;
#pragma unroll
    for (int mt = 0; mt < 2; mt++) {
        int co = mh * 128 + mw + mt * 16 + g;
        float* ob = out + (size_t)(b * 256 + co) * 3136;
        float* ob2 = ob + 8 * 3136;
#pragma unroll
        for (int nt = 0; nt < 14; nt++) {
            int n = nw + nt * 8 + t * 2;
            int r0 = n / 56, wc = n - r0 * 56;
            int off = (h0p + r0) * 56 + wc;
            float a0 = ga[off], a1 = ga[off + 1];
            ob[off] = d[mt][nt][0] * a0;
            ob[off + 1] = d[mt][nt][1] * a1;
            ob2[off] = d[mt][nt][2] * a0;
            ob2[off + 1] = d[mt][nt][3] * a1;
        }
    }
}

// ---------------------------------------------------------------------------
extern "C" void kernel_launch(void* const* d_in, const int* in_sizes, int n_in,
                              void* d_out, int out_size) {
    const float* x = (const float*)d_in[0];
    const float* weight = (const float*)d_in[1];
    const float* A_w = (const float*)d_in[2];
    const float* se_w1 = (const float*)d_in[3];
    const float* se_w2 = (const float*)d_in[4];
    float* out = (float*)d_out;

    cudaFuncSetAttribute(main_mma, cudaFuncAttributeMaxDynamicSharedMemorySize, MAIN_SMEM);
    pad_x<<<(8 * 256 * XPH * XPH + 255) / 256, 256>>>(x);
    transpose_x<<<dim3(2, 8 * 56, 8), dim3(32, 8)>>>(x);
    prep_w<<<(589824 + 36864 + 255) / 256, 256>>>(weight, A_w, se_w1);
    zero_t<<<(8 * 16 * 56 * 56 + 255) / 256, 256>>>();
    conv_se1<<<dim3(2, 14, 32), 256>>>();
    conv_se2<<<dim3(14, 8), 224>>>(se_w2);
    main_mma<<<dim3(2, 14, 8), 256, MAIN_SMEM>>>(out);
}